// round 1
// baseline (speedup 1.0000x reference)
#include <cuda_runtime.h>

#define USER_NUM 50000
#define ITEM_NUM 50000
#define N_NODES  100000
#define EMB      64
#define ADJ_NNZ  1600000
#define S_NNZ    800000
#define TOT      (N_NODES * EMB)          // 6,400,000 floats
#define TOT4     (TOT / 4)                // 1,600,000 float4s
#define USER_TOT4 (USER_NUM * EMB / 4)    // 800,000 float4s

// Scratch (allowed: __device__ globals, no runtime allocation)
__device__ float g_egoA[TOT];
__device__ float g_egoB[TOT];
__device__ float g_h[TOT];
__device__ float g_acc[TOT];

// ego = concat(user_emb, item_emb); acc = ego
__global__ void init_kernel(const float* __restrict__ ue, const float* __restrict__ ie,
                            float* __restrict__ ego, float* __restrict__ acc) {
    int i = blockIdx.x * blockDim.x + threadIdx.x;
    if (i >= TOT4) return;
    float4 v;
    if (i < USER_TOT4) v = ((const float4*)ue)[i];
    else               v = ((const float4*)ie)[i - USER_TOT4];
    ((float4*)ego)[i] = v;
    ((float4*)acc)[i] = v;
}

// h = ego; next = 0; if (add_acc) acc += ego
__global__ void prep_kernel(const float* __restrict__ ego, float* __restrict__ h,
                            float* __restrict__ nxt, float* __restrict__ acc, int add_acc) {
    int i = blockIdx.x * blockDim.x + threadIdx.x;
    if (i >= TOT4) return;
    float4 v = ((const float4*)ego)[i];
    ((float4*)h)[i]   = v;
    ((float4*)nxt)[i] = make_float4(0.f, 0.f, 0.f, 0.f);
    if (add_acc) {
        float4 a = ((const float4*)acc)[i];
        a.x += v.x; a.y += v.y; a.z += v.z; a.w += v.w;
        ((float4*)acc)[i] = a;
    }
}

// y[rows[e]] += vals[e] * x[cols[e]]   (16 threads per nnz, float4 each, vector RED)
__global__ void spmm_kernel(const int* __restrict__ rows, const int* __restrict__ cols,
                            const float* __restrict__ vals, const float* __restrict__ x,
                            float* __restrict__ y, int nnz) {
    int tid = blockIdx.x * blockDim.x + threadIdx.x;
    int e = tid >> 4;
    if (e >= nnz) return;
    int c = (tid & 15) << 2;                      // element offset within the 64-wide row
    int col = __ldg(cols + e);
    int row = __ldg(rows + e);
    float v  = __ldg(vals + e);
    float4 xv = __ldg((const float4*)(x + (size_t)col * EMB + c));
    float* dst = y + (size_t)row * EMB + c;
    asm volatile("red.global.add.v4.f32 [%0], {%1,%2,%3,%4};"
                 :: "l"(dst), "f"(xv.x * v), "f"(xv.y * v), "f"(xv.z * v), "f"(xv.w * v)
                 : "memory");
}

// out = (acc + ego) * 0.25   (final layer's acc-add fused here)
__global__ void final_kernel(const float* __restrict__ acc, const float* __restrict__ ego,
                             float* __restrict__ out) {
    int i = blockIdx.x * blockDim.x + threadIdx.x;
    if (i >= TOT4) return;
    float4 a = ((const float4*)acc)[i];
    float4 e = ((const float4*)ego)[i];
    float4 o = make_float4((a.x + e.x) * 0.25f, (a.y + e.y) * 0.25f,
                           (a.z + e.z) * 0.25f, (a.w + e.w) * 0.25f);
    ((float4*)out)[i] = o;
}

extern "C" void kernel_launch(void* const* d_in, const int* in_sizes, int n_in,
                              void* d_out, int out_size) {
    const float* ue       = (const float*)d_in[0];
    const float* ie       = (const float*)d_in[1];
    const int*   adj_rows = (const int*)d_in[2];
    const int*   adj_cols = (const int*)d_in[3];
    const float* adj_vals = (const float*)d_in[4];
    const int*   s_rows   = (const int*)d_in[5];
    const int*   s_cols   = (const int*)d_in[6];
    const float* s_vals   = (const float*)d_in[7];

    float *egoA, *egoB, *h, *acc;
    cudaGetSymbolAddress((void**)&egoA, g_egoA);
    cudaGetSymbolAddress((void**)&egoB, g_egoB);
    cudaGetSymbolAddress((void**)&h,    g_h);
    cudaGetSymbolAddress((void**)&acc,  g_acc);

    const int TPB = 256;
    const int ew_blocks = (TOT4 + TPB - 1) / TPB;

    init_kernel<<<ew_blocks, TPB>>>(ue, ie, egoA, acc);

    float* ego = egoA;
    float* nxt = egoB;
    for (int l = 0; l < 3; l++) {
        prep_kernel<<<ew_blocks, TPB>>>(ego, h, nxt, acc, l > 0);
        // u' = u + S @ u : add S@u into h[:USER_NUM], reading the unmodified ego
        {
            long long threads = (long long)S_NNZ * 16;
            spmm_kernel<<<(int)((threads + TPB - 1) / TPB), TPB>>>(
                s_rows, s_cols, s_vals, ego, h, S_NNZ);
        }
        // next = ADJ @ h
        {
            long long threads = (long long)ADJ_NNZ * 16;
            spmm_kernel<<<(int)((threads + TPB - 1) / TPB), TPB>>>(
                adj_rows, adj_cols, adj_vals, h, nxt, ADJ_NNZ);
        }
        float* t = ego; ego = nxt; nxt = t;
    }

    final_kernel<<<ew_blocks, TPB>>>(acc, ego, (float*)d_out);
}

// round 2
// speedup vs baseline: 1.7657x; 1.7657x over previous
#include <cuda_runtime.h>

#define USER_NUM 50000
#define N_NODES  100000
#define EMB      64
#define ADJ_NNZ  1600000
#define S_NNZ    800000
#define TOT      (N_NODES * EMB)
#define TOT4     (TOT / 4)
#define USER_TOT4 (USER_NUM * EMB / 4)
#define SB 512

// ---------------- scratch (device globals; no runtime allocation) ----------------
__device__ float g_egoA[TOT];
__device__ float g_egoB[TOT];
__device__ float g_h[USER_NUM * EMB];
__device__ float g_acc[TOT];

__device__ int   g_adj_cnt[N_NODES];
__device__ int   g_adj_ptr[N_NODES + 1];
__device__ int   g_adj_w[N_NODES];
__device__ int   g_adj_col[ADJ_NNZ];
__device__ float g_adj_val[ADJ_NNZ];

__device__ int   g_s_cnt[USER_NUM];
__device__ int   g_s_ptr[USER_NUM + 1];
__device__ int   g_s_w[USER_NUM];
__device__ int   g_s_col[S_NNZ];
__device__ float g_s_val[S_NNZ];

__device__ int   g_bsums[SB];

// ---------------- CSR build ----------------
__global__ void hist_kernel(const int* __restrict__ rows, int* __restrict__ cnt, int nnz) {
    int i = blockIdx.x * blockDim.x + threadIdx.x;
    if (i < nnz) atomicAdd(cnt + __ldcs(rows + i), 1);
}

// per-block exclusive scan of counts; block totals to bsums
__global__ void scan1_kernel(const int* __restrict__ cnt, int* __restrict__ ptr,
                             int* __restrict__ bsums, int n) {
    __shared__ int sh[SB];
    int i = blockIdx.x * SB + threadIdx.x;
    int v = (i < n) ? cnt[i] : 0;
    sh[threadIdx.x] = v;
    __syncthreads();
    for (int off = 1; off < SB; off <<= 1) {
        int t = (threadIdx.x >= off) ? sh[threadIdx.x - off] : 0;
        __syncthreads();
        sh[threadIdx.x] += t;
        __syncthreads();
    }
    if (i < n) ptr[i] = sh[threadIdx.x] - v;              // exclusive
    if (threadIdx.x == SB - 1) bsums[blockIdx.x] = sh[SB - 1];
}

// single-block exclusive scan of block sums (nb <= SB)
__global__ void scan2_kernel(int* __restrict__ bsums, int nb) {
    __shared__ int sh[SB];
    int v = (threadIdx.x < nb) ? bsums[threadIdx.x] : 0;
    sh[threadIdx.x] = v;
    __syncthreads();
    for (int off = 1; off < SB; off <<= 1) {
        int t = (threadIdx.x >= off) ? sh[threadIdx.x - off] : 0;
        __syncthreads();
        sh[threadIdx.x] += t;
        __syncthreads();
    }
    if (threadIdx.x < nb) bsums[threadIdx.x] = sh[threadIdx.x] - v;
}

// add block offsets; copy to working offsets; terminate rowptr
__global__ void scan3_kernel(int* __restrict__ ptr, int* __restrict__ w,
                             const int* __restrict__ bsums, int n, int nnz) {
    int i = blockIdx.x * blockDim.x + threadIdx.x;
    if (i < n) {
        int p = ptr[i] + bsums[i / SB];
        ptr[i] = p;
        w[i] = p;
    }
    if (i == 0) ptr[n] = nnz;
}

__global__ void scatter_kernel(const int* __restrict__ rows, const int* __restrict__ cols,
                               const float* __restrict__ vals, int* __restrict__ w,
                               int* __restrict__ ocol, float* __restrict__ oval, int nnz) {
    int i = blockIdx.x * blockDim.x + threadIdx.x;
    if (i >= nnz) return;
    int p = atomicAdd(w + __ldcs(rows + i), 1);
    ocol[p] = __ldcs(cols + i);
    oval[p] = __ldcs(vals + i);
}

// ---------------- elementwise init: ego = concat, acc = ego ----------------
__global__ void init_kernel(const float* __restrict__ ue, const float* __restrict__ ie,
                            float* __restrict__ ego, float* __restrict__ acc) {
    int i = blockIdx.x * blockDim.x + threadIdx.x;
    if (i >= TOT4) return;
    float4 v = (i < USER_TOT4) ? ((const float4*)ue)[i] : ((const float4*)ie)[i - USER_TOT4];
    ((float4*)ego)[i] = v;
    ((float4*)acc)[i] = v;
}

// ---------------- CSR SpMMs (16 threads per row, float4 lanes) ----------------
// h[r] = ego[r] + sum_e val * ego[col]   (users only)
__global__ void s_spmm_kernel(const int* __restrict__ ptr, const int* __restrict__ col,
                              const float* __restrict__ val, const float* __restrict__ ego,
                              float* __restrict__ h) {
    int g = (blockIdx.x * blockDim.x + threadIdx.x) >> 4;
    int lane = threadIdx.x & 15;
    if (g >= USER_NUM) return;
    int e = __ldg(ptr + g), end = __ldg(ptr + g + 1);
    float4 a = __ldg((const float4*)(ego + (size_t)g * EMB) + lane);  // self term
    for (; e + 1 < end; e += 2) {
        int   c0 = __ldcs(col + e),   c1 = __ldcs(col + e + 1);
        float w0 = __ldcs(val + e),   w1 = __ldcs(val + e + 1);
        float4 x0 = __ldg((const float4*)(ego + (size_t)c0 * EMB) + lane);
        float4 x1 = __ldg((const float4*)(ego + (size_t)c1 * EMB) + lane);
        a.x = fmaf(w0, x0.x, fmaf(w1, x1.x, a.x));
        a.y = fmaf(w0, x0.y, fmaf(w1, x1.y, a.y));
        a.z = fmaf(w0, x0.z, fmaf(w1, x1.z, a.z));
        a.w = fmaf(w0, x0.w, fmaf(w1, x1.w, a.w));
    }
    if (e < end) {
        int   c0 = __ldcs(col + e);
        float w0 = __ldcs(val + e);
        float4 x0 = __ldg((const float4*)(ego + (size_t)c0 * EMB) + lane);
        a.x = fmaf(w0, x0.x, a.x); a.y = fmaf(w0, x0.y, a.y);
        a.z = fmaf(w0, x0.z, a.z); a.w = fmaf(w0, x0.w, a.w);
    }
    ((float4*)(h + (size_t)g * EMB))[lane] = a;
}

// nxt[r] = sum_e val * sel(col);  sel = h for users, ego for items.
// epilogue: last==0 -> nxt[r]=v, acc[r]+=v ;  last==1 -> out[r]=(acc[r]+v)*0.25
__global__ void adj_spmm_kernel(const int* __restrict__ ptr, const int* __restrict__ col,
                                const float* __restrict__ val, const float* __restrict__ ego,
                                const float* __restrict__ h, float* __restrict__ nxt,
                                float* __restrict__ acc, float* __restrict__ out, int last) {
    int g = (blockIdx.x * blockDim.x + threadIdx.x) >> 4;
    int lane = threadIdx.x & 15;
    if (g >= N_NODES) return;
    int e = __ldg(ptr + g), end = __ldg(ptr + g + 1);
    float4 a = make_float4(0.f, 0.f, 0.f, 0.f);
    for (; e + 1 < end; e += 2) {
        int   c0 = __ldcs(col + e),   c1 = __ldcs(col + e + 1);
        float w0 = __ldcs(val + e),   w1 = __ldcs(val + e + 1);
        const float* b0 = (c0 < USER_NUM) ? h : ego;
        const float* b1 = (c1 < USER_NUM) ? h : ego;
        float4 x0 = __ldg((const float4*)(b0 + (size_t)c0 * EMB) + lane);
        float4 x1 = __ldg((const float4*)(b1 + (size_t)c1 * EMB) + lane);
        a.x = fmaf(w0, x0.x, fmaf(w1, x1.x, a.x));
        a.y = fmaf(w0, x0.y, fmaf(w1, x1.y, a.y));
        a.z = fmaf(w0, x0.z, fmaf(w1, x1.z, a.z));
        a.w = fmaf(w0, x0.w, fmaf(w1, x1.w, a.w));
    }
    if (e < end) {
        int   c0 = __ldcs(col + e);
        float w0 = __ldcs(val + e);
        const float* b0 = (c0 < USER_NUM) ? h : ego;
        float4 x0 = __ldg((const float4*)(b0 + (size_t)c0 * EMB) + lane);
        a.x = fmaf(w0, x0.x, a.x); a.y = fmaf(w0, x0.y, a.y);
        a.z = fmaf(w0, x0.z, a.z); a.w = fmaf(w0, x0.w, a.w);
    }
    float4 ac = __ldg((const float4*)(acc + (size_t)g * EMB) + lane);
    if (last) {
        float4 o = make_float4((ac.x + a.x) * 0.25f, (ac.y + a.y) * 0.25f,
                               (ac.z + a.z) * 0.25f, (ac.w + a.w) * 0.25f);
        ((float4*)(out + (size_t)g * EMB))[lane] = o;
    } else {
        ((float4*)(nxt + (size_t)g * EMB))[lane] = a;
        ac.x += a.x; ac.y += a.y; ac.z += a.z; ac.w += a.w;
        ((float4*)(acc + (size_t)g * EMB))[lane] = ac;
    }
}

extern "C" void kernel_launch(void* const* d_in, const int* in_sizes, int n_in,
                              void* d_out, int out_size) {
    const float* ue       = (const float*)d_in[0];
    const float* ie       = (const float*)d_in[1];
    const int*   adj_rows = (const int*)d_in[2];
    const int*   adj_cols = (const int*)d_in[3];
    const float* adj_vals = (const float*)d_in[4];
    const int*   s_rows   = (const int*)d_in[5];
    const int*   s_cols   = (const int*)d_in[6];
    const float* s_vals   = (const float*)d_in[7];

    float *egoA, *egoB, *h, *acc;
    int *adj_cnt, *adj_ptr, *adj_w, *adj_col, *s_cnt, *s_ptr, *s_w, *s_col, *bsums;
    float *adj_val, *s_val;
    cudaGetSymbolAddress((void**)&egoA,    g_egoA);
    cudaGetSymbolAddress((void**)&egoB,    g_egoB);
    cudaGetSymbolAddress((void**)&h,       g_h);
    cudaGetSymbolAddress((void**)&acc,     g_acc);
    cudaGetSymbolAddress((void**)&adj_cnt, g_adj_cnt);
    cudaGetSymbolAddress((void**)&adj_ptr, g_adj_ptr);
    cudaGetSymbolAddress((void**)&adj_w,   g_adj_w);
    cudaGetSymbolAddress((void**)&adj_col, g_adj_col);
    cudaGetSymbolAddress((void**)&adj_val, g_adj_val);
    cudaGetSymbolAddress((void**)&s_cnt,   g_s_cnt);
    cudaGetSymbolAddress((void**)&s_ptr,   g_s_ptr);
    cudaGetSymbolAddress((void**)&s_w,     g_s_w);
    cudaGetSymbolAddress((void**)&s_col,   g_s_col);
    cudaGetSymbolAddress((void**)&s_val,   g_s_val);
    cudaGetSymbolAddress((void**)&bsums,   g_bsums);

    const int TPB = 256;

    // ---- build CSR (adj) ----
    cudaMemsetAsync(adj_cnt, 0, N_NODES * sizeof(int));
    hist_kernel<<<(ADJ_NNZ + TPB - 1) / TPB, TPB>>>(adj_rows, adj_cnt, ADJ_NNZ);
    int adj_nb = (N_NODES + SB - 1) / SB;
    scan1_kernel<<<adj_nb, SB>>>(adj_cnt, adj_ptr, bsums, N_NODES);
    scan2_kernel<<<1, SB>>>(bsums, adj_nb);
    scan3_kernel<<<(N_NODES + TPB - 1) / TPB, TPB>>>(adj_ptr, adj_w, bsums, N_NODES, ADJ_NNZ);
    scatter_kernel<<<(ADJ_NNZ + TPB - 1) / TPB, TPB>>>(adj_rows, adj_cols, adj_vals,
                                                       adj_w, adj_col, adj_val, ADJ_NNZ);
    // ---- build CSR (s) ----
    cudaMemsetAsync(s_cnt, 0, USER_NUM * sizeof(int));
    hist_kernel<<<(S_NNZ + TPB - 1) / TPB, TPB>>>(s_rows, s_cnt, S_NNZ);
    int s_nb = (USER_NUM + SB - 1) / SB;
    scan1_kernel<<<s_nb, SB>>>(s_cnt, s_ptr, bsums, USER_NUM);
    scan2_kernel<<<1, SB>>>(bsums, s_nb);
    scan3_kernel<<<(USER_NUM + TPB - 1) / TPB, TPB>>>(s_ptr, s_w, bsums, USER_NUM, S_NNZ);
    scatter_kernel<<<(S_NNZ + TPB - 1) / TPB, TPB>>>(s_rows, s_cols, s_vals,
                                                     s_w, s_col, s_val, S_NNZ);

    // ---- init ----
    init_kernel<<<(TOT4 + TPB - 1) / TPB, TPB>>>(ue, ie, egoA, acc);

    // ---- 3 layers ----
    float* ego = egoA;
    float* nxt = egoB;
    const int s_blocks   = (USER_NUM * 16 + TPB - 1) / TPB;
    const int adj_blocks = (N_NODES * 16 + TPB - 1) / TPB;
    for (int l = 0; l < 3; l++) {
        s_spmm_kernel<<<s_blocks, TPB>>>(s_ptr, s_col, s_val, ego, h);
        adj_spmm_kernel<<<adj_blocks, TPB>>>(adj_ptr, adj_col, adj_val, ego, h,
                                             nxt, acc, (float*)d_out, (l == 2) ? 1 : 0);
        float* t = ego; ego = nxt; nxt = t;
    }
}

// round 3
// speedup vs baseline: 1.8064x; 1.0231x over previous
#include <cuda_runtime.h>
#include <cuda_fp16.h>

#define USER_NUM 50000
#define N_NODES  100000
#define EMB      64
#define ADJ_NNZ  1600000
#define S_NNZ    800000
#define TOT      (N_NODES * EMB)
#define SB 512

// ---------------- scratch (device globals; no runtime allocation) ----------------
__device__ __half g_egoA[TOT];
__device__ __half g_egoB[TOT];
__device__ __half g_h[USER_NUM * EMB];
__device__ float  g_acc[TOT];

__device__ int   g_adj_cnt[N_NODES];
__device__ int   g_adj_ptr[N_NODES + 1];
__device__ int   g_adj_w[N_NODES];
__device__ uint2 g_adj_cv[ADJ_NNZ];

__device__ int   g_s_cnt[USER_NUM];
__device__ int   g_s_ptr[USER_NUM + 1];
__device__ int   g_s_w[USER_NUM];
__device__ uint2 g_s_cv[S_NNZ];

__device__ int   g_bsums[SB];

// ---------------- CSR build ----------------
__global__ void hist_kernel(const int* __restrict__ rows, int* __restrict__ cnt, int nnz) {
    int i = blockIdx.x * blockDim.x + threadIdx.x;
    if (i < nnz) atomicAdd(cnt + __ldcs(rows + i), 1);
}

__global__ void scan1_kernel(const int* __restrict__ cnt, int* __restrict__ ptr,
                             int* __restrict__ bsums, int n) {
    __shared__ int sh[SB];
    int i = blockIdx.x * SB + threadIdx.x;
    int v = (i < n) ? cnt[i] : 0;
    sh[threadIdx.x] = v;
    __syncthreads();
    for (int off = 1; off < SB; off <<= 1) {
        int t = (threadIdx.x >= off) ? sh[threadIdx.x - off] : 0;
        __syncthreads();
        sh[threadIdx.x] += t;
        __syncthreads();
    }
    if (i < n) ptr[i] = sh[threadIdx.x] - v;              // exclusive
    if (threadIdx.x == SB - 1) bsums[blockIdx.x] = sh[SB - 1];
}

__global__ void scan2_kernel(int* __restrict__ bsums, int nb) {
    __shared__ int sh[SB];
    int v = (threadIdx.x < nb) ? bsums[threadIdx.x] : 0;
    sh[threadIdx.x] = v;
    __syncthreads();
    for (int off = 1; off < SB; off <<= 1) {
        int t = (threadIdx.x >= off) ? sh[threadIdx.x - off] : 0;
        __syncthreads();
        sh[threadIdx.x] += t;
        __syncthreads();
    }
    if (threadIdx.x < nb) bsums[threadIdx.x] = sh[threadIdx.x] - v;
}

__global__ void scan3_kernel(int* __restrict__ ptr, int* __restrict__ w,
                             const int* __restrict__ bsums, int n, int nnz) {
    int i = blockIdx.x * blockDim.x + threadIdx.x;
    if (i < n) {
        int p = ptr[i] + bsums[i / SB];
        ptr[i] = p;
        w[i] = p;
    }
    if (i == 0) ptr[n] = nnz;
}

__global__ void scatter_kernel(const int* __restrict__ rows, const int* __restrict__ cols,
                               const float* __restrict__ vals, int* __restrict__ w,
                               uint2* __restrict__ ocv, int nnz) {
    int i = blockIdx.x * blockDim.x + threadIdx.x;
    if (i >= nnz) return;
    int p = atomicAdd(w + __ldcs(rows + i), 1);
    ocv[p] = make_uint2((unsigned)__ldcs(cols + i), __float_as_uint(__ldcs(vals + i)));
}

// ---------------- init: ego = half(concat), acc = concat ----------------
__global__ void init_kernel(const float* __restrict__ ue, const float* __restrict__ ie,
                            __half* __restrict__ ego, float* __restrict__ acc) {
    int i = blockIdx.x * blockDim.x + threadIdx.x;   // half2 index, TOT/2 of them
    if (i >= TOT / 2) return;
    const float2* src = (i < USER_NUM * EMB / 2) ? (const float2*)ue
                                                 : (const float2*)ie - USER_NUM * EMB / 2;
    float2 v = src[i];
    ((__half2*)ego)[i] = __floats2half2_rn(v.x, v.y);
    ((float2*)acc)[i] = v;
}

// ---------------- warp-per-row SpMMs (32 lanes x half2) ----------------
// h[r] = ego[r] + sum val*ego[col]   (users)
__global__ void s_spmm_kernel(const int* __restrict__ ptr, const uint2* __restrict__ cv,
                              const __half* __restrict__ ego, __half* __restrict__ h) {
    int row = blockIdx.x * (blockDim.x >> 5) + (threadIdx.x >> 5);
    int lane = threadIdx.x & 31;
    if (row >= USER_NUM) return;
    int e = __ldg(ptr + row), end = __ldg(ptr + row + 1);
    float2 a = __half22float2(((const __half2*)(ego + (size_t)row * EMB))[lane]); // self
    for (; e + 1 < end; e += 2) {
        uint2 cv0 = __ldg(cv + e), cv1 = __ldg(cv + e + 1);
        float w0 = __uint_as_float(cv0.y), w1 = __uint_as_float(cv1.y);
        float2 x0 = __half22float2(__ldg((const __half2*)(ego + (size_t)cv0.x * EMB) + lane));
        float2 x1 = __half22float2(__ldg((const __half2*)(ego + (size_t)cv1.x * EMB) + lane));
        a.x = fmaf(w0, x0.x, fmaf(w1, x1.x, a.x));
        a.y = fmaf(w0, x0.y, fmaf(w1, x1.y, a.y));
    }
    if (e < end) {
        uint2 cv0 = __ldg(cv + e);
        float w0 = __uint_as_float(cv0.y);
        float2 x0 = __half22float2(__ldg((const __half2*)(ego + (size_t)cv0.x * EMB) + lane));
        a.x = fmaf(w0, x0.x, a.x);
        a.y = fmaf(w0, x0.y, a.y);
    }
    ((__half2*)(h + (size_t)row * EMB))[lane] = __floats2half2_rn(a.x, a.y);
}

// nxt[r] = sum val * sel(col); sel = h (users) / ego (items)
// last==0: nxt=half(v), acc+=v ;  last==1: out=(acc+v)*0.25 (fp32)
__global__ void adj_spmm_kernel(const int* __restrict__ ptr, const uint2* __restrict__ cv,
                                const __half* __restrict__ ego, const __half* __restrict__ h,
                                __half* __restrict__ nxt, float* __restrict__ acc,
                                float* __restrict__ out, int last) {
    int row = blockIdx.x * (blockDim.x >> 5) + (threadIdx.x >> 5);
    int lane = threadIdx.x & 31;
    if (row >= N_NODES) return;
    int e = __ldg(ptr + row), end = __ldg(ptr + row + 1);
    float2 a = make_float2(0.f, 0.f);
    for (; e + 1 < end; e += 2) {
        uint2 cv0 = __ldg(cv + e), cv1 = __ldg(cv + e + 1);
        float w0 = __uint_as_float(cv0.y), w1 = __uint_as_float(cv1.y);
        const __half* b0 = (cv0.x < USER_NUM) ? h : ego;
        const __half* b1 = (cv1.x < USER_NUM) ? h : ego;
        float2 x0 = __half22float2(__ldg((const __half2*)(b0 + (size_t)cv0.x * EMB) + lane));
        float2 x1 = __half22float2(__ldg((const __half2*)(b1 + (size_t)cv1.x * EMB) + lane));
        a.x = fmaf(w0, x0.x, fmaf(w1, x1.x, a.x));
        a.y = fmaf(w0, x0.y, fmaf(w1, x1.y, a.y));
    }
    if (e < end) {
        uint2 cv0 = __ldg(cv + e);
        float w0 = __uint_as_float(cv0.y);
        const __half* b0 = (cv0.x < USER_NUM) ? h : ego;
        float2 x0 = __half22float2(__ldg((const __half2*)(b0 + (size_t)cv0.x * EMB) + lane));
        a.x = fmaf(w0, x0.x, a.x);
        a.y = fmaf(w0, x0.y, a.y);
    }
    float2 ac = ((const float2*)(acc + (size_t)row * EMB))[lane];
    if (last) {
        ((float2*)(out + (size_t)row * EMB))[lane] =
            make_float2((ac.x + a.x) * 0.25f, (ac.y + a.y) * 0.25f);
    } else {
        ((__half2*)(nxt + (size_t)row * EMB))[lane] = __floats2half2_rn(a.x, a.y);
        ((float2*)(acc + (size_t)row * EMB))[lane] = make_float2(ac.x + a.x, ac.y + a.y);
    }
}

extern "C" void kernel_launch(void* const* d_in, const int* in_sizes, int n_in,
                              void* d_out, int out_size) {
    const float* ue       = (const float*)d_in[0];
    const float* ie       = (const float*)d_in[1];
    const int*   adj_rows = (const int*)d_in[2];
    const int*   adj_cols = (const int*)d_in[3];
    const float* adj_vals = (const float*)d_in[4];
    const int*   s_rows   = (const int*)d_in[5];
    const int*   s_cols   = (const int*)d_in[6];
    const float* s_vals   = (const float*)d_in[7];

    __half *egoA, *egoB, *h;
    float *acc;
    int *adj_cnt, *adj_ptr, *adj_w, *s_cnt, *s_ptr, *s_w, *bsums;
    uint2 *adj_cv, *s_cv;
    cudaGetSymbolAddress((void**)&egoA,    g_egoA);
    cudaGetSymbolAddress((void**)&egoB,    g_egoB);
    cudaGetSymbolAddress((void**)&h,       g_h);
    cudaGetSymbolAddress((void**)&acc,     g_acc);
    cudaGetSymbolAddress((void**)&adj_cnt, g_adj_cnt);
    cudaGetSymbolAddress((void**)&adj_ptr, g_adj_ptr);
    cudaGetSymbolAddress((void**)&adj_w,   g_adj_w);
    cudaGetSymbolAddress((void**)&adj_cv,  g_adj_cv);
    cudaGetSymbolAddress((void**)&s_cnt,   g_s_cnt);
    cudaGetSymbolAddress((void**)&s_ptr,   g_s_ptr);
    cudaGetSymbolAddress((void**)&s_w,     g_s_w);
    cudaGetSymbolAddress((void**)&s_cv,    g_s_cv);
    cudaGetSymbolAddress((void**)&bsums,   g_bsums);

    const int TPB = 256;

    // ---- build CSR (adj) ----
    cudaMemsetAsync(adj_cnt, 0, N_NODES * sizeof(int));
    hist_kernel<<<(ADJ_NNZ + TPB - 1) / TPB, TPB>>>(adj_rows, adj_cnt, ADJ_NNZ);
    int adj_nb = (N_NODES + SB - 1) / SB;
    scan1_kernel<<<adj_nb, SB>>>(adj_cnt, adj_ptr, bsums, N_NODES);
    scan2_kernel<<<1, SB>>>(bsums, adj_nb);
    scan3_kernel<<<(N_NODES + TPB - 1) / TPB, TPB>>>(adj_ptr, adj_w, bsums, N_NODES, ADJ_NNZ);
    scatter_kernel<<<(ADJ_NNZ + TPB - 1) / TPB, TPB>>>(adj_rows, adj_cols, adj_vals,
                                                       adj_w, adj_cv, ADJ_NNZ);
    // ---- build CSR (s) ----
    cudaMemsetAsync(s_cnt, 0, USER_NUM * sizeof(int));
    hist_kernel<<<(S_NNZ + TPB - 1) / TPB, TPB>>>(s_rows, s_cnt, S_NNZ);
    int s_nb = (USER_NUM + SB - 1) / SB;
    scan1_kernel<<<s_nb, SB>>>(s_cnt, s_ptr, bsums, USER_NUM);
    scan2_kernel<<<1, SB>>>(bsums, s_nb);
    scan3_kernel<<<(USER_NUM + TPB - 1) / TPB, TPB>>>(s_ptr, s_w, bsums, USER_NUM, S_NNZ);
    scatter_kernel<<<(S_NNZ + TPB - 1) / TPB, TPB>>>(s_rows, s_cols, s_vals,
                                                     s_w, s_cv, S_NNZ);

    // ---- init ----
    init_kernel<<<(TOT / 2 + TPB - 1) / TPB, TPB>>>(ue, ie, egoA, acc);

    // ---- 3 layers ----
    __half* ego = egoA;
    __half* nxt = egoB;
    const int warps_per_block = TPB / 32;
    const int s_blocks   = (USER_NUM + warps_per_block - 1) / warps_per_block;
    const int adj_blocks = (N_NODES + warps_per_block - 1) / warps_per_block;
    for (int l = 0; l < 3; l++) {
        s_spmm_kernel<<<s_blocks, TPB>>>(s_ptr, s_cv, ego, h);
        adj_spmm_kernel<<<adj_blocks, TPB>>>(adj_ptr, adj_cv, ego, h,
                                             nxt, acc, (float*)d_out, (l == 2) ? 1 : 0);
        __half* t = ego; ego = nxt; nxt = t;
    }
}